// round 11
// baseline (speedup 1.0000x reference)
#include <cuda_runtime.h>
#include <cuda_pipeline_primitives.h>
#include <math.h>
#include <stdint.h>

#define FULLMASK 0xffffffffu
#define B_ 4
#define A_ 16
#define NL_ 4096
#define DE_ 256
#define DH_ 64
#define H_ 8
#define STAGES 6

// Scratch (__device__ globals; allocation-free rule)
__device__ float g_qW[64 * H_ * DE_];     // wq = lnkw ⊙ qW, per (ba,h)
__device__ float g_c[64 * 16];            // c1[ba][h], c2[ba][h]
__device__ float g_vals[B_ * NL_ * DH_];  // logmap0(demo_hyp)
__device__ float g_mh[B_ * H_ * A_ * DH_];

__device__ __forceinline__ float warp_sum(float v) {
    v += __shfl_xor_sync(FULLMASK, v, 16);
    v += __shfl_xor_sync(FULLMASK, v, 8);
    v += __shfl_xor_sync(FULLMASK, v, 4);
    v += __shfl_xor_sync(FULLMASK, v, 2);
    v += __shfl_xor_sync(FULLMASK, v, 1);
    return v;
}

// ---- packed f32x2 helpers (sm_103a FFMA2 path; IEEE-exact per lane) ----
__device__ __forceinline__ uint64_t pack2(float lo, float hi) {
    uint64_t r; asm("mov.b64 %0, {%1, %2};" : "=l"(r) : "f"(lo), "f"(hi)); return r;
}
__device__ __forceinline__ void unpack2(uint64_t v, float& lo, float& hi) {
    asm("mov.b64 {%0, %1}, %2;" : "=f"(lo), "=f"(hi) : "l"(v));
}
__device__ __forceinline__ uint64_t fma2(uint64_t a, uint64_t b, uint64_t c) {
    uint64_t d; asm("fma.rn.f32x2 %0, %1, %2, %3;" : "=l"(d) : "l"(a), "l"(b), "l"(c)); return d;
}
__device__ __forceinline__ uint64_t mul2(uint64_t a, uint64_t b) {
    uint64_t d; asm("mul.rn.f32x2 %0, %1, %2;" : "=l"(d) : "l"(a), "l"(b)); return d;
}
__device__ __forceinline__ uint64_t add2(uint64_t a, uint64_t b) {
    uint64_t d; asm("add.rn.f32x2 %0, %1, %2;" : "=l"(d) : "l"(a), "l"(b)); return d;
}

// ============================================================================
// K1 (merged prep): blocks 0..63 -> qW/c1/c2; blocks 64..2111 -> vals + zero mh
// ============================================================================
__global__ void __launch_bounds__(256) k_prep(
    const float* __restrict__ curr, const float* __restrict__ Wq,
    const float* __restrict__ Wk, const float* __restrict__ lqw,
    const float* __restrict__ lqb, const float* __restrict__ lkw,
    const float* __restrict__ lkb, const float* __restrict__ hyp)
{
    const int tid = threadIdx.x;
    const int warp = tid >> 5, lane = tid & 31;
    if (blockIdx.x >= 64) {
        const int bi = blockIdx.x - 64;
        const int gw = bi * 8 + warp;    // 0..16383 rows
        const float2 v = ((const float2*)(hyp + (size_t)gw * DH_))[lane];
        float nn = warp_sum(v.x * v.x + v.y * v.y);
        float n = fmaxf(sqrtf(nn), 1e-15f);
        float u = fminf(n, 1.0f - 1e-5f);
        float f = atanhf(u) / n;
        float2 o; o.x = v.x * f; o.y = v.y * f;
        ((float2*)(g_vals + (size_t)gw * DH_))[lane] = o;
        const int idx = bi * 256 + tid;
        if (idx < B_ * H_ * A_ * DH_) g_mh[idx] = 0.f;
        return;
    }
    __shared__ float sred[256];
    __shared__ float sln[256];
    __shared__ float sq[256];
    __shared__ float spart[8][16];
    const int ba = blockIdx.x;
    float x = curr[ba * 256 + tid];
    sred[tid] = x; __syncthreads();
    for (int s = 128; s > 0; s >>= 1) { if (tid < s) sred[tid] += sred[tid + s]; __syncthreads(); }
    float mu = sred[0] * (1.f / 256.f); __syncthreads();
    float d = x - mu;
    sred[tid] = d * d; __syncthreads();
    for (int s = 128; s > 0; s >>= 1) { if (tid < s) sred[tid] += sred[tid + s]; __syncthreads(); }
    float var = sred[0] * (1.f / 256.f);
    sln[tid] = d * rsqrtf(var + 1e-5f) * lqw[tid] + lqb[tid];
    __syncthreads();

    float acc = 0.f;
    const float4* wr = (const float4*)(Wq + tid * 256);
    const float4* lr = (const float4*)sln;
#pragma unroll 8
    for (int i = 0; i < 64; i++) {
        float4 w = wr[i]; float4 l = lr[i];
        acc += w.x * l.x + w.y * l.y + w.z * l.z + w.w * l.w;
    }
    sq[tid] = acc; __syncthreads();

    const float scale = 0.17677669529663689f;  // 1/sqrt(32)
    const float mw = lkw[tid], mb = lkb[tid];
    float vh[8];
#pragma unroll
    for (int h = 0; h < 8; h++) {
        float v = 0.f;
#pragma unroll
        for (int dd = 0; dd < 32; dd++)
            v += sq[h * 32 + dd] * Wk[(h * 32 + dd) * 256 + tid];
        vh[h] = v * scale;
        g_qW[(ba * 8 + h) * 256 + tid] = vh[h] * mw;
    }
#pragma unroll
    for (int h = 0; h < 8; h++) {
        float r1 = warp_sum(vh[h] * mw);
        float r2 = warp_sum(vh[h] * mb);
        if (lane == 0) { spart[warp][h] = r1; spart[warp][h + 8] = r2; }
    }
    __syncthreads();
    if (tid < 16) {
        float s = 0.f;
#pragma unroll
        for (int w = 0; w < 8; w++) s += spart[w][tid];
        g_c[ba * 16 + tid] = s;
    }
}

// ============================================================================
// K2: scores. Warp per row; qW register-resident (as f32x2 pairs); algebraic
// LN fold; batched multi-value shuffle reduction; cp.async 6-stage pipeline
// one row/iter (R8/R10 structure). Dot/sum/ssq computed with packed
// fma.rn.f32x2 — halves fma-pipe occupancy, bit-identical fp32 lanes.
// launch_bounds(256,2): do NOT raise minBlocks (42-reg cap spilled, R4).
// ============================================================================
#define MERGE(out, lo, hi, pd, dd) { \
    float _sel = (pd) ? (hi) : (lo); \
    float _oth = (pd) ? (lo) : (hi); \
    out = _sel + __shfl_xor_sync(FULLMASK, _oth, dd); }

__device__ __forceinline__ void process_row(
    const float4 f0, const float4 f1, const int j,
    const int lane, const bool pb1, const bool pb2, const bool pb4,
    const uint64_t* __restrict__ qw,   // [8][4] packed pairs
    const float myc1, const float myc2, float* __restrict__ stw)
{
    uint64_t r0 = pack2(f0.x, f0.y), r1 = pack2(f0.z, f0.w);
    uint64_t r2 = pack2(f1.x, f1.y), r3 = pack2(f1.z, f1.w);

    // sum & ssq via packed pairs
    uint64_t s2 = add2(add2(r0, r1), add2(r2, r3));
    uint64_t q2 = mul2(r0, r0); q2 = fma2(r1, r1, q2);
    q2 = fma2(r2, r2, q2);      q2 = fma2(r3, r3, q2);
    float slo, shi, qlo, qhi;
    unpack2(s2, slo, shi); unpack2(q2, qlo, qhi);
    float sum = slo + shi, ssq = qlo + qhi;

    float acc[8];
#pragma unroll
    for (int h = 0; h < 8; h++) {
        uint64_t a2 = mul2(r0, qw[h * 4 + 0]);
        a2 = fma2(r1, qw[h * 4 + 1], a2);
        a2 = fma2(r2, qw[h * 4 + 2], a2);
        a2 = fma2(r3, qw[h * 4 + 3], a2);
        float lo, hi; unpack2(a2, lo, hi);
        acc[h] = lo + hi;
    }
    // interleaved multi-value reduction: lane ends holding acc[lane&7] (full)
    float m0, m1, m2, m3, n0, n1, p;
    MERGE(m0, acc[0], acc[1], pb1, 1); MERGE(m1, acc[2], acc[3], pb1, 1);
    MERGE(m2, acc[4], acc[5], pb1, 1); MERGE(m3, acc[6], acc[7], pb1, 1);
    MERGE(n0, m0, m1, pb2, 2); MERGE(n1, m2, m3, pb2, 2);
    MERGE(p, n0, n1, pb4, 4);
    p += __shfl_xor_sync(FULLMASK, p, 8);
    p += __shfl_xor_sync(FULLMASK, p, 16);
    // sum/ssq pair reduction
    float t; MERGE(t, sum, ssq, pb1, 1);
    t += __shfl_xor_sync(FULLMASK, t, 2);
    t += __shfl_xor_sync(FULLMASK, t, 4);
    t += __shfl_xor_sync(FULLMASK, t, 8);
    t += __shfl_xor_sync(FULLMASK, t, 16);
    float o = __shfl_xor_sync(FULLMASK, t, 1);
    float sT = pb1 ? o : t;
    float qT = pb1 ? t : o;
    float mu  = sT * (1.f / 256.f);
    float inv = rsqrtf(fmaf(-mu, mu, qT * (1.f / 256.f)) + 1e-5f);
    float sc  = fmaf(inv, fmaf(-mu, myc1, p), myc2);
    if (lane < 8) stw[lane * 33 + j] = sc;
}

__global__ void __launch_bounds__(256, 2) k_scores(
    const float* __restrict__ rho, const int* __restrict__ mask,
    float* __restrict__ attn)
{
    __shared__ float srow[8][STAGES][256];   // 48 KB: 6-row pipeline per warp
    __shared__ float stile[8][8 * 33];
    const int warp = threadIdx.x >> 5, lane = threadIdx.x & 31;
    const int gw = blockIdx.x * 8 + warp;
    const int ba = gw >> 7, chunk = gw & 127;
    const int b = ba >> 4, a = ba & 15;
    const int x0 = chunk << 5;

    uint64_t qw[32];   // [8 heads][4 pairs] = same 64-reg footprint as before
#pragma unroll
    for (int h = 0; h < 8; h++) {
        const float4* p = (const float4*)(g_qW + (ba * 8 + h) * 256);
        const float4 a4 = p[lane], b4 = p[32 + lane];
        qw[h * 4 + 0] = pack2(a4.x, a4.y); qw[h * 4 + 1] = pack2(a4.z, a4.w);
        qw[h * 4 + 2] = pack2(b4.x, b4.y); qw[h * 4 + 3] = pack2(b4.z, b4.w);
    }
    const float myc1 = g_c[ba * 16 + (lane & 7)];
    const float myc2 = g_c[ba * 16 + 8 + (lane & 7)];
    const int mymask = mask[b * NL_ + x0 + lane];
    const bool pb1 = lane & 1, pb2 = lane & 2, pb4 = lane & 4;
    float* stw = &stile[warp][0];

    const float* base = rho + ((size_t)(b * NL_ + x0) * 16 + a) * 256;

    // prologue: fill the pipeline (rows 0..5)
#pragma unroll
    for (int s = 0; s < STAGES; s++) {
        const float4* src = (const float4*)(base + (size_t)s * 4096);
        __pipeline_memcpy_async(&srow[warp][s][lane * 4],       &src[lane],      16);
        __pipeline_memcpy_async(&srow[warp][s][128 + lane * 4], &src[32 + lane], 16);
        __pipeline_commit();
    }

    int st = 0;
#pragma unroll 1
    for (int j = 0; j < 32; j++) {
        __pipeline_wait_prior(STAGES - 1);
        const float4 r0 = *(const float4*)&srow[warp][st][lane * 4];
        const float4 r1 = *(const float4*)&srow[warp][st][128 + lane * 4];
        if (j + STAGES < 32) {  // refill this stage (own bytes only)
            const float4* src = (const float4*)(base + (size_t)(j + STAGES) * 4096);
            __pipeline_memcpy_async(&srow[warp][st][lane * 4],       &src[lane],      16);
            __pipeline_memcpy_async(&srow[warp][st][128 + lane * 4], &src[32 + lane], 16);
        }
        __pipeline_commit();
        process_row(r0, r1, j, lane, pb1, pb2, pb4, qw, myc1, myc2, stw);
        if (++st == STAGES) st = 0;
    }
    __syncwarp();
#pragma unroll
    for (int h = 0; h < 8; h++) {
        float v = stw[h * 33 + lane];
        attn[((size_t)((b * 8 + h) * 16 + a)) * NL_ + x0 + lane] = mymask ? v : -INFINITY;
    }
}

// ============================================================================
// K3: softmax, register-resident float4 per thread, 1024 threads/block
// ============================================================================
__global__ void __launch_bounds__(1024) k_softmax(float* __restrict__ attn)
{
    __shared__ float sred[32];
    const int tid = threadIdx.x, lane = tid & 31, wid = tid >> 5;
    float4* p = (float4*)(attn + (size_t)blockIdx.x * NL_);
    float4 v = p[tid];
    float mx = fmaxf(fmaxf(v.x, v.y), fmaxf(v.z, v.w));
    for (int d = 16; d; d >>= 1) mx = fmaxf(mx, __shfl_xor_sync(FULLMASK, mx, d));
    if (lane == 0) sred[wid] = mx;
    __syncthreads();
    if (wid == 0) {
        float m = sred[lane];
        for (int d = 16; d; d >>= 1) m = fmaxf(m, __shfl_xor_sync(FULLMASK, m, d));
        if (lane == 0) sred[0] = m;
    }
    __syncthreads();
    mx = sred[0];
    __syncthreads();
    v.x = __expf(v.x - mx); v.y = __expf(v.y - mx);
    v.z = __expf(v.z - mx); v.w = __expf(v.w - mx);
    float s = (v.x + v.y) + (v.z + v.w);
    for (int d = 16; d; d >>= 1) s += __shfl_xor_sync(FULLMASK, s, d);
    if (lane == 0) sred[wid] = s;
    __syncthreads();
    if (wid == 0) {
        float m = sred[lane];
        for (int d = 16; d; d >>= 1) m += __shfl_xor_sync(FULLMASK, m, d);
        if (lane == 0) sred[0] = m;
    }
    __syncthreads();
    const float inv = 1.0f / sred[0];
    v.x *= inv; v.y *= inv; v.z *= inv; v.w *= inv;
    p[tid] = v;
}

// ============================================================================
// K5: m_h = attn @ vals (R8/R10 structure, f32x2 accumulate: 8 FFMA2/j
// instead of 16 FFMA). Shuffle-broadcast; warp owns EIGHT a-rows;
// grid (B,H,32); spread-address atomics are cheap (R9 lesson: no rewrite).
// ============================================================================
__global__ void __launch_bounds__(256) k_mh(const float* __restrict__ attn)
{
    const int b = blockIdx.x, h = blockIdx.y, xs = blockIdx.z;  // xs 0..31
    const int warp = threadIdx.x >> 5, lane = threadIdx.x & 31;
    const int sub = warp & 3;            // 32-x chunk within the 128-x slice
    const int a0 = (warp >> 2) * 8;      // 8 a-rows per warp
    const int x0 = xs * 128 + sub * 32;

    const float* arow = attn + ((size_t)((b * 8 + h) * 16 + a0)) * NL_ + x0;
    float att[8];
#pragma unroll
    for (int i = 0; i < 8; i++) att[i] = arow[(size_t)i * NL_ + lane];

    const uint64_t* vp = (const uint64_t*)(g_vals + ((size_t)(b * NL_) + x0) * 64) + lane;
    uint64_t acc2[8] = {0ull, 0ull, 0ull, 0ull, 0ull, 0ull, 0ull, 0ull};
#pragma unroll 8
    for (int j = 0; j < 32; j++) {
        const uint64_t v2 = vp[j * 32];
#pragma unroll
        for (int i = 0; i < 8; i++) {
            const float av = __shfl_sync(FULLMASK, att[i], j);
            acc2[i] = fma2(pack2(av, av), v2, acc2[i]);
        }
    }
    float* m0 = g_mh + ((size_t)(b * 8 + h) * 16 + a0) * 64 + 2 * lane;
#pragma unroll
    for (int i = 0; i < 8; i++) {
        float ax, ay; unpack2(acc2[i], ax, ay);
        atomicAdd(m0 + i * 64,     ax);
        atomicAdd(m0 + i * 64 + 1, ay);
    }
}

// ============================================================================
// K6: tail — log/exp maps, means, radius clamp
// ============================================================================
__global__ void __launch_bounds__(256) k_tail(float* __restrict__ out)
{
    __shared__ float shyp[16][DH_];
    const int b = blockIdx.x;
    const int warp = threadIdx.x >> 5, lane = threadIdx.x & 31;

    for (int ai = 0; ai < 2; ai++) {
        const int a = warp + ai * 8;
        float t0 = 0.f, t1 = 0.f;
        for (int h = 0; h < H_; h++) {
            const float2 m = ((const float2*)(g_mh + ((size_t)(b * H_ + h) * 16 + a) * DH_))[lane];
            float nn = warp_sum(m.x * m.x + m.y * m.y);
            float n = fmaxf(sqrtf(nn), 1e-15f);
            float ce = tanhf(n) / n;
            float ex = m.x * ce, ey = m.y * ce;
            float nn2 = warp_sum(ex * ex + ey * ey);
            float n2 = fmaxf(sqrtf(nn2), 1e-15f);
            float u = fminf(n2, 1.0f - 1e-5f);
            float f = atanhf(u) / n2;
            t0 += ex * f; t1 += ey * f;
        }
        t0 *= (1.0f / H_); t1 *= (1.0f / H_);
        float nn = warp_sum(t0 * t0 + t1 * t1);
        float n = fmaxf(sqrtf(nn), 1e-15f);
        float ce = tanhf(n) / n;
        float cx = t0 * ce, cy = t1 * ce;
        float nn2 = warp_sum(cx * cx + cy * cy);
        float nc = fmaxf(sqrtf(nn2), 1e-6f);
        float sc = fminf((1.0f - 1e-5f) / nc, 1.0f);
        shyp[a][lane * 2] = cx * sc;
        shyp[a][lane * 2 + 1] = cy * sc;
    }
    __syncthreads();
    if (threadIdx.x < DH_) {
        float s = 0.f;
        for (int a = 0; a < 16; a++) s += shyp[a][threadIdx.x];
        out[b * DH_ + threadIdx.x] = s * (1.0f / 16.0f);
    }
}

// ============================================================================
extern "C" void kernel_launch(void* const* d_in, const int* in_sizes, int n_in,
                              void* d_out, int out_size)
{
    const float* curr = (const float*)d_in[0];
    const float* rho  = (const float*)d_in[1];
    const float* hyp  = (const float*)d_in[2];
    const int*   mask = (const int*)d_in[3];
    const float* Wq   = (const float*)d_in[4];
    const float* Wk   = (const float*)d_in[5];
    const float* lqw  = (const float*)d_in[6];
    const float* lqb  = (const float*)d_in[7];
    const float* lkw  = (const float*)d_in[8];
    const float* lkb  = (const float*)d_in[9];

    float* out  = (float*)d_out;
    float* attn = out + B_ * DH_;

    k_prep<<<2112, 256>>>(curr, Wq, Wk, lqw, lqb, lkw, lkb, hyp);
    k_scores<<<1024, 256>>>(rho, mask, attn);
    k_softmax<<<512, 1024>>>(attn);
    dim3 g5(B_, H_, 32);
    k_mh<<<g5, 256>>>(attn);
    k_tail<<<B_, 256>>>(out);
}